// round 1
// baseline (speedup 1.0000x reference)
#include <cuda_runtime.h>
#include <cstdint>
#include <cstddef>

#define N_CAP 50000
#define E_CAP 1600000
#define NCOL  640

// Scratch (static __device__ — no allocation in kernel_launch)
__device__ float gU[128 * NCOL];
__device__ float gC[NCOL];
__device__ float gY[(size_t)N_CAP * NCOL];   // 128 MB node feature packs
__device__ int   gCount[N_CAP];
__device__ int   gOff[N_CAP + 1];
__device__ int   gCur[N_CAP];
__device__ int   gCsr[E_CAP];

// ---------------------------------------------------------------------------
// Zero per-node edge counts
// ---------------------------------------------------------------------------
__global__ void zero_kernel(int N) {
    int i = blockIdx.x * blockDim.x + threadIdx.x;
    if (i < N) gCount[i] = 0;
}

// ---------------------------------------------------------------------------
// Fold weights:  U[k][col], c[col]
//   cols [0,256):   A heads  U = Wt_i @ Wa_i[0:64,:]   (bias: bt@Wa_top + bt@Wa_bot + ba)
//   cols [256,512): B heads  U = Wt_i @ Wa_i[64:128,:] (bias 0)
//   cols [512,576): Xn  (Wn, bn)
//   cols [576,640): Xv  (Wv, bv)
// ---------------------------------------------------------------------------
__global__ void prep_kernel(const float* __restrict__ Wv, const float* __restrict__ bv,
                            const float* __restrict__ Wn, const float* __restrict__ bn,
                            const float* __restrict__ Wt, const float* __restrict__ bt,
                            const float* __restrict__ Wa, const float* __restrict__ ba) {
    int tid = blockIdx.x * blockDim.x + threadIdx.x;
    if (tid < 128 * NCOL) {
        int k = tid / NCOL;
        int col = tid % NCOL;
        float v;
        if (col < 512) {
            int top = (col < 256) ? 1 : 0;
            int i = (col >> 6) & 3;
            int j = col & 63;
            const float* wt = Wt + ((size_t)i * 128 + k) * 64;        // Wt[i][k][*]
            const float* wa = Wa + (size_t)i * 128 * 64 + (top ? 0 : 64 * 64) + j;
            float s = 0.f;
            #pragma unroll 8
            for (int m = 0; m < 64; m++) s += wt[m] * wa[m * 64];
            v = s;
        } else if (col < 576) {
            v = Wn[k * 64 + (col - 512)];
        } else {
            v = Wv[k * 64 + (col - 576)];
        }
        gU[tid] = v;
    }
    if (tid < NCOL) {
        float c;
        if (tid < 256) {
            int i = tid >> 6, j = tid & 63;
            const float* btp = bt + i * 64;
            const float* wa = Wa + (size_t)i * 128 * 64 + j;
            float s = ba[i * 64 + j];
            #pragma unroll 8
            for (int m = 0; m < 64; m++)
                s += btp[m] * (wa[m * 64] + wa[(64 + m) * 64]);
            c = s;
        } else if (tid < 512) {
            c = 0.f;
        } else if (tid < 576) {
            c = bn[tid - 512];
        } else {
            c = bv[tid - 576];
        }
        gC[tid] = c;
    }
}

// ---------------------------------------------------------------------------
// Node GEMM: Y[M x 640] = X[M x 128] @ U[128 x 640] + c
// Tiled fp32: BM=64 BN=64 BK=16, 256 threads, 4x4 per thread
// ---------------------------------------------------------------------------
#define BM 64
#define BN 64
#define BK 16

__global__ __launch_bounds__(256) void gemm_kernel(const float* __restrict__ X, int M) {
    __shared__ float As[BK][BM + 4];
    __shared__ float Bs[BK][BN];

    int bm = blockIdx.x * BM;
    int bn = blockIdx.y * BN;
    int tid = threadIdx.x;
    int tx = tid & 15;       // N dim
    int ty = tid >> 4;       // M dim

    float acc[4][4];
    #pragma unroll
    for (int i = 0; i < 4; i++)
        #pragma unroll
        for (int j = 0; j < 4; j++) acc[i][j] = 0.f;

    for (int k0 = 0; k0 < 128; k0 += BK) {
        // A tile: 64 rows x 16 k. one float4 per thread.
        {
            int r = tid >> 2;            // 0..63
            int c4 = (tid & 3) << 2;     // 0,4,8,12
            int row = bm + r;
            float4 v = make_float4(0.f, 0.f, 0.f, 0.f);
            if (row < M) v = *(const float4*)(X + (size_t)row * 128 + k0 + c4);
            As[c4 + 0][r] = v.x;
            As[c4 + 1][r] = v.y;
            As[c4 + 2][r] = v.z;
            As[c4 + 3][r] = v.w;
        }
        // B tile: 16 k x 64 cols. one float4 per thread.
        {
            int r = tid >> 4;            // 0..15 (k)
            int c4 = (tid & 15) << 2;    // 0..60
            float4 v = *(const float4*)(gU + (size_t)(k0 + r) * NCOL + bn + c4);
            *(float4*)&Bs[r][c4] = v;
        }
        __syncthreads();
        #pragma unroll
        for (int k = 0; k < BK; k++) {
            float am[4], bv_[4];
            #pragma unroll
            for (int i = 0; i < 4; i++) am[i] = As[k][ty * 4 + i];
            #pragma unroll
            for (int j = 0; j < 4; j++) bv_[j] = Bs[k][tx * 4 + j];
            #pragma unroll
            for (int i = 0; i < 4; i++)
                #pragma unroll
                for (int j = 0; j < 4; j++)
                    acc[i][j] = fmaf(am[i], bv_[j], acc[i][j]);
        }
        __syncthreads();
    }

    int colb = bn + tx * 4;
    float4 cb = *(const float4*)(gC + colb);
    #pragma unroll
    for (int i = 0; i < 4; i++) {
        int row = bm + ty * 4 + i;
        if (row < M) {
            float4 o;
            o.x = acc[i][0] + cb.x;
            o.y = acc[i][1] + cb.y;
            o.z = acc[i][2] + cb.z;
            o.w = acc[i][3] + cb.w;
            *(float4*)(gY + (size_t)row * NCOL + colb) = o;
        }
    }
}

// ---------------------------------------------------------------------------
// CSR build
// ---------------------------------------------------------------------------
__global__ void count_kernel(const int* __restrict__ dst, int E) {
    int i = blockIdx.x * blockDim.x + threadIdx.x;
    if (i < E) atomicAdd(&gCount[dst[i]], 1);
}

__global__ void scan_kernel(int N) {
    __shared__ int sm[1024];
    int tid = threadIdx.x;
    int chunk = (N + 1023) / 1024;
    int start = tid * chunk;
    int end = start + chunk;
    if (end > N) end = N;
    if (start > N) start = N;
    int s = 0;
    for (int i = start; i < end; i++) s += gCount[i];
    sm[tid] = s;
    __syncthreads();
    // Hillis-Steele inclusive scan
    for (int off = 1; off < 1024; off <<= 1) {
        int v = (tid >= off) ? sm[tid - off] : 0;
        __syncthreads();
        sm[tid] += v;
        __syncthreads();
    }
    int run = (tid == 0) ? 0 : sm[tid - 1];
    for (int i = start; i < end; i++) {
        gOff[i] = run;
        gCur[i] = run;
        run += gCount[i];
    }
    if (tid == 1023) gOff[N] = sm[1023];
}

__global__ void scatter_kernel(const int* __restrict__ src, const int* __restrict__ dst, int E) {
    int i = blockIdx.x * blockDim.x + threadIdx.x;
    if (i < E) {
        int p = atomicAdd(&gCur[dst[i]], 1);
        gCsr[p] = src[i];
    }
}

// ---------------------------------------------------------------------------
// Aggregation: one warp per dst node, each thread owns 2 output channels.
// Y row layout per node: [A0..A3 | B0..B3 | Xn | Xv] (640 floats)
// ---------------------------------------------------------------------------
__global__ __launch_bounds__(256) void aggregate_kernel(float* __restrict__ out, int N) {
    int w = (blockIdx.x * blockDim.x + threadIdx.x) >> 5;
    int lane = threadIdx.x & 31;
    if (w >= N) return;
    const float* rowD = gY + (size_t)w * NCOL;
    int c = lane * 2;

    float2 a0 = *(const float2*)(rowD + 0 + c);
    float2 a1 = *(const float2*)(rowD + 64 + c);
    float2 a2 = *(const float2*)(rowD + 128 + c);
    float2 a3 = *(const float2*)(rowD + 192 + c);
    float2 s0 = *(const float2*)(rowD + 256 + c);
    float2 s1 = *(const float2*)(rowD + 320 + c);
    float2 s2 = *(const float2*)(rowD + 384 + c);
    float2 s3 = *(const float2*)(rowD + 448 + c);
    float2 xv = *(const float2*)(rowD + 576 + c);

    const float Kc = 0.25f * 1.4426950408889634f;  // log2(e)/4

    float sx = fmaxf(a0.x + s0.x, 0.f) + fmaxf(a1.x + s1.x, 0.f) +
               fmaxf(a2.x + s2.x, 0.f) + fmaxf(a3.x + s3.x, 0.f);
    float sy = fmaxf(a0.y + s0.y, 0.f) + fmaxf(a1.y + s1.y, 0.f) +
               fmaxf(a2.y + s2.y, 0.f) + fmaxf(a3.y + s3.y, 0.f);
    float ex = exp2f(sx * Kc), ey = exp2f(sy * Kc);
    float denx = ex, deny = ey;
    float numx = ex * xv.x, numy = ey * xv.y;

    int j = gOff[w];
    int end = gOff[w + 1];
    #pragma unroll 2
    for (; j < end; j++) {
        int s = gCsr[j];
        const float* rs = gY + (size_t)s * NCOL + 256;
        float2 b0 = *(const float2*)(rs + 0 + c);
        float2 b1 = *(const float2*)(rs + 64 + c);
        float2 b2 = *(const float2*)(rs + 128 + c);
        float2 b3 = *(const float2*)(rs + 192 + c);
        float2 xn = *(const float2*)(rs + 256 + c);
        float tx = fmaxf(a0.x + b0.x, 0.f) + fmaxf(a1.x + b1.x, 0.f) +
                   fmaxf(a2.x + b2.x, 0.f) + fmaxf(a3.x + b3.x, 0.f);
        float ty = fmaxf(a0.y + b0.y, 0.f) + fmaxf(a1.y + b1.y, 0.f) +
                   fmaxf(a2.y + b2.y, 0.f) + fmaxf(a3.y + b3.y, 0.f);
        float g1 = exp2f(tx * Kc);
        float g2 = exp2f(ty * Kc);
        denx += g1;
        deny += g2;
        numx = fmaf(g1, xn.x, numx);
        numy = fmaf(g2, xn.y, numy);
    }

    float2 o;
    o.x = fmaxf(numx / denx, 0.f);
    o.y = fmaxf(numy / deny, 0.f);
    *(float2*)(out + (size_t)w * 64 + c) = o;
}

// ---------------------------------------------------------------------------
// Launch
// ---------------------------------------------------------------------------
extern "C" void kernel_launch(void* const* d_in, const int* in_sizes, int n_in,
                              void* d_out, int out_size) {
    const float* x   = (const float*)d_in[0];
    const int*   src = (const int*)d_in[1];
    const int*   dst = (const int*)d_in[2];
    const float* Wv  = (const float*)d_in[3];
    const float* bv  = (const float*)d_in[4];
    const float* Wn  = (const float*)d_in[5];
    const float* bn  = (const float*)d_in[6];
    const float* Wt  = (const float*)d_in[7];
    const float* bt  = (const float*)d_in[8];
    const float* Wa  = (const float*)d_in[9];
    const float* ba  = (const float*)d_in[10];
    float* out = (float*)d_out;

    int N = in_sizes[0] / 128;
    int E = in_sizes[1];

    zero_kernel<<<(N + 255) / 256, 256>>>(N);
    prep_kernel<<<(128 * NCOL + 255) / 256, 256>>>(Wv, bv, Wn, bn, Wt, bt, Wa, ba);
    dim3 gg((N + BM - 1) / BM, NCOL / BN);
    gemm_kernel<<<gg, 256>>>(x, N);
    count_kernel<<<(E + 255) / 256, 256>>>(dst, E);
    scan_kernel<<<1, 1024>>>(N);
    scatter_kernel<<<(E + 255) / 256, 256>>>(src, dst, E);
    aggregate_kernel<<<(N * 32 + 255) / 256, 256>>>(out, N);
}

// round 2
// speedup vs baseline: 1.4033x; 1.4033x over previous
#include <cuda_runtime.h>
#include <cstdint>
#include <cstddef>

#define N_CAP 50000
#define E_CAP 1600000
#define NCOL  640
#define HCOL  320

// Scratch (static __device__ — no allocation in kernel_launch)
__device__ float gU[128 * NCOL];
__device__ float gC[NCOL];
__device__ float gYdst[(size_t)N_CAP * HCOL];   // [A0..A3 | Xv]
__device__ float gYsrc[(size_t)N_CAP * HCOL];   // [B0..B3 | Xn]
__device__ int   gCount[N_CAP];
__device__ int   gOff[N_CAP + 1];
__device__ int   gCur[N_CAP];
__device__ int   gCsr[E_CAP];

// ---------------------------------------------------------------------------
__global__ void zero_kernel(int N) {
    int i = blockIdx.x * blockDim.x + threadIdx.x;
    if (i < N) gCount[i] = 0;
}

// ---------------------------------------------------------------------------
// Fold weights into U'[128 x 640], c[640]
// col layout: [A heads: 0-255 | Xv: 256-319 | B heads: 320-575 | Xn: 576-639]
//   A_i = Wt_i @ Wa_i[0:64,:]    bias: ba_i + bt_i@(Wa_top + Wa_bot)
//   B_i = Wt_i @ Wa_i[64:128,:]  bias 0
// ---------------------------------------------------------------------------
__global__ void prep_kernel(const float* __restrict__ Wv, const float* __restrict__ bv,
                            const float* __restrict__ Wn, const float* __restrict__ bn,
                            const float* __restrict__ Wt, const float* __restrict__ bt,
                            const float* __restrict__ Wa, const float* __restrict__ ba) {
    int tid = blockIdx.x * blockDim.x + threadIdx.x;
    if (tid < 128 * NCOL) {
        int k = tid / NCOL;
        int col = tid % NCOL;
        float v;
        if (col < 256 || (col >= 320 && col < 576)) {
            int top = (col < 256) ? 1 : 0;
            int cc = top ? col : (col - 320);
            int i = (cc >> 6) & 3;
            int j = cc & 63;
            const float* wt = Wt + ((size_t)i * 128 + k) * 64;        // Wt[i][k][*]
            const float* wa = Wa + (size_t)i * 128 * 64 + (top ? 0 : 64 * 64) + j;
            float s = 0.f;
            #pragma unroll 8
            for (int m = 0; m < 64; m++) s += wt[m] * wa[m * 64];
            v = s;
        } else if (col < 320) {
            v = Wv[k * 64 + (col - 256)];
        } else {
            v = Wn[k * 64 + (col - 576)];
        }
        gU[tid] = v;
    }
    if (tid < NCOL) {
        float c;
        if (tid < 256) {
            int i = tid >> 6, j = tid & 63;
            const float* btp = bt + i * 64;
            const float* wa = Wa + (size_t)i * 128 * 64 + j;
            float s = ba[i * 64 + j];
            #pragma unroll 8
            for (int m = 0; m < 64; m++)
                s += btp[m] * (wa[m * 64] + wa[(64 + m) * 64]);
            c = s;
        } else if (tid < 320) {
            c = bv[tid - 256];
        } else if (tid < 576) {
            c = 0.f;
        } else {
            c = bn[tid - 576];
        }
        gC[tid] = c;
    }
}

// ---------------------------------------------------------------------------
// TF32 tensor-core GEMM: Y[M x 640] = X[M x 128] @ U'[128 x 640] + c
// BM=128, BN=64, full K=128 resident in smem. 8 warps, 32x32 per warp,
// m16n8k8 tf32 mma. Output routed to gYdst (cols<320) or gYsrc.
// ---------------------------------------------------------------------------
#define A_LD 132
#define B_LD 72
#define GEMM_SMEM ((128 * A_LD + 128 * B_LD) * 4)

__device__ __forceinline__ uint32_t f2tf32(float f) {
    uint32_t r;
    asm("cvt.rna.tf32.f32 %0, %1;" : "=r"(r) : "f"(f));
    return r;
}

__global__ __launch_bounds__(256) void gemm_tc_kernel(const float* __restrict__ X, int M) {
    extern __shared__ float smem[];
    float* As = smem;                 // [128][132]
    float* Bs = smem + 128 * A_LD;    // [128][72]

    int tid = threadIdx.x;
    int bm = blockIdx.x * 128;
    int bnblk = blockIdx.y * 64;

    // --- Load A tile (128 x 128), converted to tf32 bits ---
    #pragma unroll
    for (int it = 0; it < 16; it++) {
        int idx = tid + it * 256;         // 0..4095 float4 slots
        int r = idx >> 5;
        int c4 = (idx & 31) << 2;
        float4 v = make_float4(0.f, 0.f, 0.f, 0.f);
        if (bm + r < M) v = *(const float4*)(X + (size_t)(bm + r) * 128 + c4);
        float4 o;
        o.x = __uint_as_float(f2tf32(v.x));
        o.y = __uint_as_float(f2tf32(v.y));
        o.z = __uint_as_float(f2tf32(v.z));
        o.w = __uint_as_float(f2tf32(v.w));
        *(float4*)(As + r * A_LD + c4) = o;
    }
    // --- Load B tile (128 k x 64 n) ---
    #pragma unroll
    for (int it = 0; it < 8; it++) {
        int idx = tid + it * 256;         // 0..2047 float4 slots
        int k = idx >> 4;
        int c4 = (idx & 15) << 2;
        float4 v = *(const float4*)(gU + (size_t)k * NCOL + bnblk + c4);
        float4 o;
        o.x = __uint_as_float(f2tf32(v.x));
        o.y = __uint_as_float(f2tf32(v.y));
        o.z = __uint_as_float(f2tf32(v.z));
        o.w = __uint_as_float(f2tf32(v.w));
        *(float4*)(Bs + k * B_LD + c4) = o;
    }
    __syncthreads();

    int w = tid >> 5, lane = tid & 31;
    int g = lane >> 2, tig = lane & 3;
    int wm = (w >> 1) * 32;   // 4 warps along M
    int wn = (w & 1) * 32;    // 2 warps along N

    float acc[2][4][4];
    #pragma unroll
    for (int mt = 0; mt < 2; mt++)
        #pragma unroll
        for (int nt = 0; nt < 4; nt++)
            #pragma unroll
            for (int q = 0; q < 4; q++) acc[mt][nt][q] = 0.f;

    #pragma unroll
    for (int kc = 0; kc < 16; kc++) {
        int kb = kc * 8;
        uint32_t a[2][4], b[4][2];
        #pragma unroll
        for (int mt = 0; mt < 2; mt++) {
            int r0 = wm + mt * 16 + g;
            a[mt][0] = __float_as_uint(As[r0 * A_LD + kb + tig]);
            a[mt][1] = __float_as_uint(As[(r0 + 8) * A_LD + kb + tig]);
            a[mt][2] = __float_as_uint(As[r0 * A_LD + kb + tig + 4]);
            a[mt][3] = __float_as_uint(As[(r0 + 8) * A_LD + kb + tig + 4]);
        }
        #pragma unroll
        for (int nt = 0; nt < 4; nt++) {
            int n0 = wn + nt * 8 + g;
            b[nt][0] = __float_as_uint(Bs[(kb + tig) * B_LD + n0]);
            b[nt][1] = __float_as_uint(Bs[(kb + tig + 4) * B_LD + n0]);
        }
        #pragma unroll
        for (int mt = 0; mt < 2; mt++)
            #pragma unroll
            for (int nt = 0; nt < 4; nt++) {
                asm volatile(
                    "mma.sync.aligned.m16n8k8.row.col.f32.tf32.tf32.f32 "
                    "{%0,%1,%2,%3}, {%4,%5,%6,%7}, {%8,%9}, {%0,%1,%2,%3};\n"
                    : "+f"(acc[mt][nt][0]), "+f"(acc[mt][nt][1]),
                      "+f"(acc[mt][nt][2]), "+f"(acc[mt][nt][3])
                    : "r"(a[mt][0]), "r"(a[mt][1]), "r"(a[mt][2]), "r"(a[mt][3]),
                      "r"(b[nt][0]), "r"(b[nt][1]));
            }
    }

    // --- Epilogue: add bias, route to Ydst / Ysrc ---
    float* outBase;
    int colofs;
    if (bnblk < HCOL) { outBase = gYdst; colofs = bnblk; }
    else              { outBase = gYsrc; colofs = bnblk - HCOL; }

    #pragma unroll
    for (int nt = 0; nt < 4; nt++) {
        int cg = wn + nt * 8 + tig * 2;            // col in 64-block
        float bx = gC[bnblk + cg];
        float by = gC[bnblk + cg + 1];
        #pragma unroll
        for (int mt = 0; mt < 2; mt++) {
            int r0 = bm + wm + mt * 16 + g;
            if (r0 < M) {
                float2 o0 = { acc[mt][nt][0] + bx, acc[mt][nt][1] + by };
                *(float2*)(outBase + (size_t)r0 * HCOL + colofs + cg) = o0;
            }
            int r1 = r0 + 8;
            if (r1 < M) {
                float2 o1 = { acc[mt][nt][2] + bx, acc[mt][nt][3] + by };
                *(float2*)(outBase + (size_t)r1 * HCOL + colofs + cg) = o1;
            }
        }
    }
}

// ---------------------------------------------------------------------------
// CSR build
// ---------------------------------------------------------------------------
__global__ void count_kernel(const int* __restrict__ dst, int E) {
    int i = blockIdx.x * blockDim.x + threadIdx.x;
    if (i < E) atomicAdd(&gCount[dst[i]], 1);
}

__global__ void scan_kernel(int N) {
    __shared__ int sm[1024];
    int tid = threadIdx.x;
    int chunk = (N + 1023) / 1024;
    int start = tid * chunk;
    int end = start + chunk;
    if (end > N) end = N;
    if (start > N) start = N;
    int s = 0;
    for (int i = start; i < end; i++) s += gCount[i];
    sm[tid] = s;
    __syncthreads();
    for (int off = 1; off < 1024; off <<= 1) {
        int v = (tid >= off) ? sm[tid - off] : 0;
        __syncthreads();
        sm[tid] += v;
        __syncthreads();
    }
    int run = (tid == 0) ? 0 : sm[tid - 1];
    for (int i = start; i < end; i++) {
        gOff[i] = run;
        gCur[i] = run;
        run += gCount[i];
    }
    if (tid == 1023) gOff[N] = sm[1023];
}

__global__ void scatter_kernel(const int* __restrict__ src, const int* __restrict__ dst, int E) {
    int i = blockIdx.x * blockDim.x + threadIdx.x;
    if (i < E) {
        int p = atomicAdd(&gCur[dst[i]], 1);
        gCsr[p] = src[i];
    }
}

// ---------------------------------------------------------------------------
// Aggregation: one warp per dst node, each thread owns 2 output channels.
// gYdst row: [A0..A3 | Xv], gYsrc row: [B0..B3 | Xn] (320 floats each)
// ---------------------------------------------------------------------------
__global__ __launch_bounds__(256) void aggregate_kernel(float* __restrict__ out, int N) {
    int w = (blockIdx.x * blockDim.x + threadIdx.x) >> 5;
    int lane = threadIdx.x & 31;
    if (w >= N) return;
    const float* rowD = gYdst + (size_t)w * HCOL;
    const float* rowS = gYsrc + (size_t)w * HCOL;
    int c = lane * 2;

    float2 a0 = *(const float2*)(rowD + 0 + c);
    float2 a1 = *(const float2*)(rowD + 64 + c);
    float2 a2 = *(const float2*)(rowD + 128 + c);
    float2 a3 = *(const float2*)(rowD + 192 + c);
    float2 xv = *(const float2*)(rowD + 256 + c);
    float2 s0 = *(const float2*)(rowS + 0 + c);
    float2 s1 = *(const float2*)(rowS + 64 + c);
    float2 s2 = *(const float2*)(rowS + 128 + c);
    float2 s3 = *(const float2*)(rowS + 192 + c);

    const float Kc = 0.25f * 1.4426950408889634f;  // log2(e)/4

    float sx = fmaxf(a0.x + s0.x, 0.f) + fmaxf(a1.x + s1.x, 0.f) +
               fmaxf(a2.x + s2.x, 0.f) + fmaxf(a3.x + s3.x, 0.f);
    float sy = fmaxf(a0.y + s0.y, 0.f) + fmaxf(a1.y + s1.y, 0.f) +
               fmaxf(a2.y + s2.y, 0.f) + fmaxf(a3.y + s3.y, 0.f);
    float ex = exp2f(sx * Kc), ey = exp2f(sy * Kc);
    float denx = ex, deny = ey;
    float numx = ex * xv.x, numy = ey * xv.y;

    int j = gOff[w];
    int end = gOff[w + 1];
    #pragma unroll 2
    for (; j < end; j++) {
        int s = gCsr[j];
        const float* rs = gYsrc + (size_t)s * HCOL;
        float2 b0 = *(const float2*)(rs + 0 + c);
        float2 b1 = *(const float2*)(rs + 64 + c);
        float2 b2 = *(const float2*)(rs + 128 + c);
        float2 b3 = *(const float2*)(rs + 192 + c);
        float2 xn = *(const float2*)(rs + 256 + c);
        float tx = fmaxf(a0.x + b0.x, 0.f) + fmaxf(a1.x + b1.x, 0.f) +
                   fmaxf(a2.x + b2.x, 0.f) + fmaxf(a3.x + b3.x, 0.f);
        float ty = fmaxf(a0.y + b0.y, 0.f) + fmaxf(a1.y + b1.y, 0.f) +
                   fmaxf(a2.y + b2.y, 0.f) + fmaxf(a3.y + b3.y, 0.f);
        float g1 = exp2f(tx * Kc);
        float g2 = exp2f(ty * Kc);
        denx += g1;
        deny += g2;
        numx = fmaf(g1, xn.x, numx);
        numy = fmaf(g2, xn.y, numy);
    }

    float2 o;
    o.x = fmaxf(numx / denx, 0.f);
    o.y = fmaxf(numy / deny, 0.f);
    *(float2*)(out + (size_t)w * 64 + c) = o;
}

// ---------------------------------------------------------------------------
// Launch
// ---------------------------------------------------------------------------
extern "C" void kernel_launch(void* const* d_in, const int* in_sizes, int n_in,
                              void* d_out, int out_size) {
    const float* x   = (const float*)d_in[0];
    const int*   src = (const int*)d_in[1];
    const int*   dst = (const int*)d_in[2];
    const float* Wv  = (const float*)d_in[3];
    const float* bv  = (const float*)d_in[4];
    const float* Wn  = (const float*)d_in[5];
    const float* bn  = (const float*)d_in[6];
    const float* Wt  = (const float*)d_in[7];
    const float* bt  = (const float*)d_in[8];
    const float* Wa  = (const float*)d_in[9];
    const float* ba  = (const float*)d_in[10];
    float* out = (float*)d_out;

    int N = in_sizes[0] / 128;
    int E = in_sizes[1];

    static bool attr_set = false;
    if (!attr_set) {
        cudaFuncSetAttribute(gemm_tc_kernel,
                             cudaFuncAttributeMaxDynamicSharedMemorySize, GEMM_SMEM);
        attr_set = true;
    }

    zero_kernel<<<(N + 255) / 256, 256>>>(N);
    prep_kernel<<<(128 * NCOL + 255) / 256, 256>>>(Wv, bv, Wn, bn, Wt, bt, Wa, ba);
    dim3 gg((N + 127) / 128, NCOL / 64);
    gemm_tc_kernel<<<gg, 256, GEMM_SMEM>>>(x, N);
    count_kernel<<<(E + 255) / 256, 256>>>(dst, E);
    scan_kernel<<<1, 1024>>>(N);
    scatter_kernel<<<(E + 255) / 256, 256>>>(src, dst, E);
    aggregate_kernel<<<(N * 32 + 255) / 256, 256>>>(out, N);
}